// round 10
// baseline (speedup 1.0000x reference)
#include <cuda_runtime.h>

#define B_ 64
#define J_ 25
#define V_ 50000
#define VT 128          // threads per skin block
#define VPT 3           // vertices per thread (consecutive)
#define VT2 (VT*VPT)    // 384 vertices per block
#define NB 8            // batches per skin block
#define NPAIR (NB/2)
#define BPB 32          // batches per fk block

// Scratch (device global; no allocation allowed)
__device__ float g_T[B_*J_*12];   // per-(b,j) skinning transform (3x4 row-major)

// ---------------------------------------------------------------------------
// FK kernel: 2 blocks x 1024 threads, 32 batches per block. Locals in smem,
// 96 threads run the sequential chain with smem-only reads.
// ---------------------------------------------------------------------------
__global__ __launch_bounds__(1024)
void fk_kernel(const float* __restrict__ je,
               const float* __restrict__ lp,
               const float* __restrict__ sc,
               const float* __restrict__ gpi,
               const int* __restrict__ parents,
               float* __restrict__ joint_out) {
    __shared__ float ls[BPB * J_ * 12];
    __shared__ float gpis[J_ * 16];
    __shared__ int   par[J_];

    int tid = threadIdx.x;
    int bbase = blockIdx.x * BPB;

    if (tid < J_ * 16) gpis[tid] = gpi[tid];
    if (tid < J_) par[tid] = parents[tid];

    for (int idx = tid; idx < BPB * J_; idx += blockDim.x) {
        int j = idx % J_;
        int gidx = bbase * J_ + idx;
        float ex = je[gidx*3+0], ey = je[gidx*3+1], ez = je[gidx*3+2];
        float sx, cx, sy, cy, sz, cz;
        sincosf(ex, &sx, &cx);
        sincosf(ey, &sy, &cy);
        sincosf(ez, &sz, &cz);
        float R00 = cz*cy, R01 = cz*sy*sx - sz*cx, R02 = cz*sy*cx + sz*sx;
        float R10 = sz*cy, R11 = sz*sy*sx + cz*cx, R12 = sz*sy*cx - cz*sx;
        float R20 = -sy,   R21 = cy*sx,            R22 = cy*cx;
        const float* L0 = lp + j*16;
        float* out = ls + idx*12;
        #pragma unroll
        for (int r = 0; r < 3; ++r) {
            float a0 = L0[r*4+0], a1 = L0[r*4+1], a2 = L0[r*4+2];
            out[r*4+0] = a0*R00 + a1*R10 + a2*R20;
            out[r*4+1] = a0*R01 + a1*R11 + a2*R21;
            out[r*4+2] = a0*R02 + a1*R12 + a2*R22;
            out[r*4+3] = L0[r*4+3] + sc[j*3+r];
        }
    }

    __syncthreads();

    if (tid >= BPB * 3) return;
    int bl = tid / 3, r = tid % 3;
    int b = bbase + bl;

    float Grow[J_][4];
    float pr0 = 0.f, pr1 = 0.f, pr2 = 0.f, pr3 = 0.f;
    int prevj = -2;
    for (int j = 0; j < J_; ++j) {
        int pj = par[j];
        float g0, g1, g2, g3;
        if (pj < 0) {
            g0 = (r == 0) ? 1.f : 0.f;
            g1 = (r == 1) ? 1.f : 0.f;
            g2 = (r == 2) ? 1.f : 0.f;
            g3 = 0.f;
        } else {
            float p0, p1, p2, p3;
            if (pj == prevj) { p0 = pr0; p1 = pr1; p2 = pr2; p3 = pr3; }
            else { p0 = Grow[pj][0]; p1 = Grow[pj][1]; p2 = Grow[pj][2]; p3 = Grow[pj][3]; }
            const float* L = ls + (bl*J_ + j) * 12;
            g0 = p0*L[0] + p1*L[4] + p2*L[8];
            g1 = p0*L[1] + p1*L[5] + p2*L[9];
            g2 = p0*L[2] + p1*L[6] + p2*L[10];
            g3 = p0*L[3] + p1*L[7] + p2*L[11] + p3;
        }
        Grow[j][0] = g0; Grow[j][1] = g1; Grow[j][2] = g2; Grow[j][3] = g3;
        pr0 = g0; pr1 = g1; pr2 = g2; pr3 = g3; prevj = j;

        const float* P = gpis + j*16;
        float4 t4;
        t4.x = g0*P[0] + g1*P[4] + g2*P[8];
        t4.y = g0*P[1] + g1*P[5] + g2*P[9];
        t4.z = g0*P[2] + g1*P[6] + g2*P[10];
        t4.w = g0*P[3] + g1*P[7] + g2*P[11] + g3;
        *reinterpret_cast<float4*>(g_T + (b*J_ + j)*12 + r*4) = t4;
        joint_out[(b*J_ + j)*3 + r] = g3;
    }
}

// ---------------------------------------------------------------------------
// f32x2 packed helpers (sm_100+)
// ---------------------------------------------------------------------------
__device__ __forceinline__ unsigned long long pack2(float lo, float hi) {
    unsigned long long d;
    asm("mov.b64 %0, {%1, %2};" : "=l"(d)
        : "r"(__float_as_uint(lo)), "r"(__float_as_uint(hi)));
    return d;
}
__device__ __forceinline__ unsigned long long pack2s(float w) {
    unsigned long long d;
    asm("mov.b64 %0, {%1, %1};" : "=l"(d) : "r"(__float_as_uint(w)));
    return d;
}
__device__ __forceinline__ void unpack2(unsigned long long s, float& lo, float& hi) {
    unsigned int a, b;
    asm("mov.b64 {%0, %1}, %2;" : "=r"(a), "=r"(b) : "l"(s));
    lo = __uint_as_float(a); hi = __uint_as_float(b);
}
__device__ __forceinline__ void fma2acc(unsigned long long& d,
                                        unsigned long long a,
                                        unsigned long long b) {
    asm("fma.rn.f32x2 %0, %1, %2, %0;" : "+l"(d) : "l"(a), "l"(b));
}
__device__ __forceinline__ unsigned long long fma2(unsigned long long a,
                                                   unsigned long long b,
                                                   unsigned long long c) {
    unsigned long long d;
    asm("fma.rn.f32x2 %0, %1, %2, %3;" : "=l"(d) : "l"(a), "l"(b), "l"(c));
    return d;
}

// ---------------------------------------------------------------------------
// Skinning kernel. 128 threads x 3 consecutive vertices/thread = 384 vertices
// per block, x 8 batches (4 batch pairs). f32x2 accumulators packed over the
// batch pair; each broadcast T LDS.128 feeds THREE vertices (36 FFMA2 per
// 9 LDS per joint -> FMA becomes the near-binder). Corrective LDG issued at
// the top of each pair-iteration, consumed after the j-loop.
// Smem: ws 38.4KB + Ts 9.6KB = 48.0KB (static limit 48KB).
// ---------------------------------------------------------------------------
__global__ __launch_bounds__(VT, 3)
void skin_kernel(const float* __restrict__ vtx,
                 const float* __restrict__ W,
                 const float* __restrict__ pc,
                 const float* __restrict__ ic,
                 float* __restrict__ mesh_out) {
    __shared__ float ws[VT2 * J_];                        // 38.4 KB, row-major
    __shared__ __align__(16) float2 Ts[NPAIR * J_ * 12];  // 9.6 KB

    int tid = threadIdx.x;
    int v0 = blockIdx.x * VT2;
    int b0base = blockIdx.y * NB;
    int nv = min(VT2, V_ - v0);

    // Stage weights (contiguous, coalesced). Rows >= nv stay uninitialized
    // (read but never stored).
    for (int i = tid; i < nv * J_; i += VT)
        ws[i] = W[(size_t)v0 * J_ + i];

    // Stage T for NB batches, interleaved per batch pair
    for (int i = tid; i < NPAIR * J_ * 12; i += VT) {
        int p = i / (J_ * 12);
        int rem = i - p * (J_ * 12);
        int b0 = b0base + 2 * p;
        Ts[i] = make_float2(g_T[b0 * (J_*12) + rem],
                            g_T[(b0 + 1) * (J_*12) + rem]);
    }
    __syncthreads();

    int lv = VPT * tid;            // local vertex base
    if (lv >= nv) return;          // no further __syncthreads
    bool val1 = (lv + 1 < nv);
    bool val2 = (lv + 2 < nv);
    int vA = v0 + lv;

    // Vertex coords (guarded)
    float vx0 = vtx[vA*3+0], vy0 = vtx[vA*3+1], vz0 = vtx[vA*3+2];
    float vx1 = 0.f, vy1 = 0.f, vz1 = 0.f, vx2 = 0.f, vy2 = 0.f, vz2 = 0.f;
    if (val1) { vx1 = vtx[vA*3+3]; vy1 = vtx[vA*3+4]; vz1 = vtx[vA*3+5]; }
    if (val2) { vx2 = vtx[vA*3+6]; vy2 = vtx[vA*3+7]; vz2 = vtx[vA*3+8]; }

    const int strideB = V_ * 3;                          // 150000
    const int base = b0base * strideB + vA * 3;          // fits int

    const float* wb0 = ws + lv * J_;
    const float* wb1 = wb0 + J_;
    const float* wb2 = wb0 + 2 * J_;

    #pragma unroll 1
    for (int p = 0; p < NPAIR; ++p) {
        int o0 = base + (2 * p) * strideB;   // batch b0
        int o1 = o0 + strideB;               // batch b1

        // ---- issue corrective loads FIRST (consumed after the j-loop) ----
        float dp0[9], dp1[9], di0[9], di1[9];
        #pragma unroll
        for (int k = 0; k < 3; ++k) {
            dp0[k] = pc[o0+k]; dp1[k] = pc[o1+k];
            di0[k] = ic[o0+k]; di1[k] = ic[o1+k];
        }
        #pragma unroll
        for (int k = 3; k < 6; ++k) {
            dp0[k] = val1 ? pc[o0+k] : 0.f; dp1[k] = val1 ? pc[o1+k] : 0.f;
            di0[k] = val1 ? ic[o0+k] : 0.f; di1[k] = val1 ? ic[o1+k] : 0.f;
        }
        #pragma unroll
        for (int k = 6; k < 9; ++k) {
            dp0[k] = val2 ? pc[o0+k] : 0.f; dp1[k] = val2 ? pc[o1+k] : 0.f;
            di0[k] = val2 ? ic[o0+k] : 0.f; di1[k] = val2 ? ic[o1+k] : 0.f;
        }

        // ---- blend: M_i = sum_j w_i[j] * T[pair j] ----
        unsigned long long M0[12], M1[12], M2[12];
        #pragma unroll
        for (int k = 0; k < 12; ++k) { M0[k] = 0ull; M1[k] = 0ull; M2[k] = 0ull; }

        const ulonglong2* tb =
            reinterpret_cast<const ulonglong2*>(Ts + p * (J_ * 12));
        #pragma unroll 5
        for (int j = 0; j < J_; ++j) {
            unsigned long long wp0 = pack2s(wb0[j]);
            unsigned long long wp1 = pack2s(wb1[j]);
            unsigned long long wp2 = pack2s(wb2[j]);
            const ulonglong2* trow = tb + j * 6;   // 12 u64 = 6 x 16B
            #pragma unroll
            for (int m = 0; m < 6; ++m) {
                ulonglong2 q = trow[m];
                fma2acc(M0[2*m], q.x, wp0); fma2acc(M0[2*m+1], q.y, wp0);
                fma2acc(M1[2*m], q.x, wp1); fma2acc(M1[2*m+1], q.y, wp1);
                fma2acc(M2[2*m], q.x, wp2); fma2acc(M2[2*m+1], q.y, wp2);
            }
        }

        // ---- apply per vertex, coords packed over {b0, b1} ----
        {
            unsigned long long px, py, pz, o;
            float s0, s1;

            // vertex 0
            px = pack2(vx0 + dp0[0] + di0[0], vx0 + dp1[0] + di1[0]);
            py = pack2(vy0 + dp0[1] + di0[1], vy0 + dp1[1] + di1[1]);
            pz = pack2(vz0 + dp0[2] + di0[2], vz0 + dp1[2] + di1[2]);
            #pragma unroll
            for (int r = 0; r < 3; ++r) {
                o = fma2(M0[4*r+2], pz, M0[4*r+3]);
                o = fma2(M0[4*r+1], py, o);
                o = fma2(M0[4*r+0], px, o);
                unpack2(o, s0, s1);
                mesh_out[o0 + r] = s0;
                mesh_out[o1 + r] = s1;
            }
            // vertex 1
            if (val1) {
                px = pack2(vx1 + dp0[3] + di0[3], vx1 + dp1[3] + di1[3]);
                py = pack2(vy1 + dp0[4] + di0[4], vy1 + dp1[4] + di1[4]);
                pz = pack2(vz1 + dp0[5] + di0[5], vz1 + dp1[5] + di1[5]);
                #pragma unroll
                for (int r = 0; r < 3; ++r) {
                    o = fma2(M1[4*r+2], pz, M1[4*r+3]);
                    o = fma2(M1[4*r+1], py, o);
                    o = fma2(M1[4*r+0], px, o);
                    unpack2(o, s0, s1);
                    mesh_out[o0 + 3 + r] = s0;
                    mesh_out[o1 + 3 + r] = s1;
                }
            }
            // vertex 2
            if (val2) {
                px = pack2(vx2 + dp0[6] + di0[6], vx2 + dp1[6] + di1[6]);
                py = pack2(vy2 + dp0[7] + di0[7], vy2 + dp1[7] + di1[7]);
                pz = pack2(vz2 + dp0[8] + di0[8], vz2 + dp1[8] + di1[8]);
                #pragma unroll
                for (int r = 0; r < 3; ++r) {
                    o = fma2(M2[4*r+2], pz, M2[4*r+3]);
                    o = fma2(M2[4*r+1], py, o);
                    o = fma2(M2[4*r+0], px, o);
                    unpack2(o, s0, s1);
                    mesh_out[o0 + 6 + r] = s0;
                    mesh_out[o1 + 6 + r] = s1;
                }
            }
        }
    }
}

// ---------------------------------------------------------------------------
extern "C" void kernel_launch(void* const* d_in, const int* in_sizes, int n_in,
                              void* d_out, int out_size) {
    const float* joint_euler = (const float*)d_in[0];
    const float* vtx         = (const float*)d_in[1];
    const float* W           = (const float*)d_in[2];
    const float* local_pose  = (const float*)d_in[3];
    const float* gpi         = (const float*)d_in[4];
    const float* sc          = (const float*)d_in[5];
    const float* pc          = (const float*)d_in[6];
    const float* ic          = (const float*)d_in[7];
    const int*   parents     = (const int*)d_in[8];
    float* out = (float*)d_out;

    fk_kernel<<<B_ / BPB, 1024>>>(joint_euler, local_pose, sc, gpi, parents, out);
    dim3 grid((V_ + VT2 - 1) / VT2, B_ / NB);
    skin_kernel<<<grid, VT>>>(vtx, W, pc, ic, out + B_*J_*3);
}